// round 13
// baseline (speedup 1.0000x reference)
#include <cuda_runtime.h>
#include <cuda_bf16.h>
#include <math.h>

// Problem constants
#define VOCAB 50000
#define DIM   512
#define SEQL  512
#define BATCH 256
#define NCLS  20

// smem layout (floats): wt[64][516] rotated+transposed Wh slice, hs[16][516]
#define CSTR  516
#define RNN_SMEM_FLOATS ((64 + 16) * CSTR)
#define RNN_SMEM_BYTES  (RNN_SMEM_FLOATS * 4)   // 165,120 B
#define RNN_THREADS 128

typedef unsigned long long ull;

// ---------------- device scratch (no runtime alloc allowed) ----------------
__device__ float g_embW[(size_t)VOCAB * DIM];       // emb @ Wx + b, ~100 MB
__device__ float g_h[2 * BATCH * DIM];              // ping-pong hidden state
__device__ unsigned g_flags[16][32];                // per-CTA step flags (8 used/group)

// strong acquire/release flag ops (R7/R11-proven protocol)
__device__ __forceinline__ unsigned ldflag_acq(const unsigned* p) {
    unsigned v;
    asm volatile("ld.acquire.gpu.global.u32 %0, [%1];" : "=r"(v) : "l"(p) : "memory");
    return v;
}
__device__ __forceinline__ void stflag_rel(unsigned* p, unsigned v) {
    asm volatile("st.release.gpu.global.u32 [%0], %1;" :: "l"(p), "r"(v) : "memory");
}

// hardware tanh (MUFU.TANH): max err ~2^-11 abs; recurrence is contractive
// (measured fp32 chain: per-step 1e-6 -> final 3e-7), expected final ~1e-4.
__device__ __forceinline__ float tanhfast(float x) {
    float y;
    asm("tanh.approx.f32 %0, %1;" : "=f"(y) : "f"(x));
    return y;
}

// packed fp32x2 math (sm_103a native; ptxas never auto-generates these)
__device__ __forceinline__ ull fma2(ull a, ull b, ull c) {
    ull d;
    asm("fma.rn.f32x2 %0, %1, %2, %3;" : "=l"(d) : "l"(a), "l"(b), "l"(c));
    return d;
}
__device__ __forceinline__ ull add2(ull a, ull b) {
    ull d;
    asm("add.rn.f32x2 %0, %1, %2;" : "=l"(d) : "l"(a), "l"(b));
    return d;
}
__device__ __forceinline__ ull shflx64(ull v, int m) {
    unsigned lo = (unsigned)v, hi = (unsigned)(v >> 32);
    lo = __shfl_xor_sync(0xffffffffu, lo, m);
    hi = __shfl_xor_sync(0xffffffffu, hi, m);
    return ((ull)hi << 32) | (ull)lo;
}

// ---------------- kernel 1: embW = emb @ Wx + b  (fp32 tiled GEMM) ----------
// BM=128, BN=128, BK=16, 256 threads, 8x8 per thread; 2 CTAs/SM target.
__global__ __launch_bounds__(256, 2) void embw_gemm(
    const float* __restrict__ A,    // emb [M][512]
    const float* __restrict__ B,    // Wx  [512][512]
    const float* __restrict__ bias, // b [512]
    int M)
{
    __shared__ float As[16][132];   // transposed A tile [k][m], padded
    __shared__ float Bs[16][128];   // [k][n]

    const int tid  = threadIdx.x;
    const int row0 = blockIdx.y * 128;
    const int col0 = blockIdx.x * 128;
    const int tm = tid >> 4;        // 0..15 -> 8 rows each
    const int tn = tid & 15;        // 0..15 -> cols tn*4 and 64+tn*4

    float4 acc0[8], acc1[8];
    #pragma unroll
    for (int i = 0; i < 8; i++) {
        acc0[i] = make_float4(0.f, 0.f, 0.f, 0.f);
        acc1[i] = make_float4(0.f, 0.f, 0.f, 0.f);
    }

    for (int k0 = 0; k0 < DIM; k0 += 16) {
        #pragma unroll
        for (int t = 0; t < 2; t++) {
            int idx = tid + t * 256;
            int am  = idx >> 2;
            int ak4 = (idx & 3) << 2;
            float4 av = make_float4(0.f, 0.f, 0.f, 0.f);
            if (row0 + am < M)
                av = *(const float4*)(A + (size_t)(row0 + am) * DIM + k0 + ak4);
            As[ak4 + 0][am] = av.x;
            As[ak4 + 1][am] = av.y;
            As[ak4 + 2][am] = av.z;
            As[ak4 + 3][am] = av.w;
        }
        #pragma unroll
        for (int t = 0; t < 2; t++) {
            int idx = tid + t * 256;
            int bk  = idx >> 5;
            int bn4 = (idx & 31) << 2;
            *(float4*)&Bs[bk][bn4] =
                *(const float4*)(B + (size_t)(k0 + bk) * DIM + col0 + bn4);
        }
        __syncthreads();

        #pragma unroll
        for (int kk = 0; kk < 16; kk++) {
            float4 b0 = *(const float4*)&Bs[kk][tn << 2];
            float4 b1 = *(const float4*)&Bs[kk][64 + (tn << 2)];
            float4 a0 = *(const float4*)&As[kk][tm * 8];
            float4 a1 = *(const float4*)&As[kk][tm * 8 + 4];
            float av[8] = {a0.x, a0.y, a0.z, a0.w, a1.x, a1.y, a1.z, a1.w};
            #pragma unroll
            for (int i = 0; i < 8; i++) {
                acc0[i].x += av[i] * b0.x; acc0[i].y += av[i] * b0.y;
                acc0[i].z += av[i] * b0.z; acc0[i].w += av[i] * b0.w;
                acc1[i].x += av[i] * b1.x; acc1[i].y += av[i] * b1.y;
                acc1[i].z += av[i] * b1.z; acc1[i].w += av[i] * b1.w;
            }
        }
        __syncthreads();
    }

    float4 bb0 = *(const float4*)(bias + col0 + (tn << 2));
    float4 bb1 = *(const float4*)(bias + col0 + 64 + (tn << 2));
    #pragma unroll
    for (int i = 0; i < 8; i++) {
        int row = row0 + tm * 8 + i;
        if (row < M) {
            float4 o0, o1;
            o0.x = acc0[i].x + bb0.x; o0.y = acc0[i].y + bb0.y;
            o0.z = acc0[i].z + bb0.z; o0.w = acc0[i].w + bb0.w;
            o1.x = acc1[i].x + bb1.x; o1.y = acc1[i].y + bb1.y;
            o1.z = acc1[i].z + bb1.z; o1.w = acc1[i].w + bb1.w;
            *(float4*)(g_embW + (size_t)row * DIM + col0 + (tn << 2))      = o0;
            *(float4*)(g_embW + (size_t)row * DIM + col0 + 64 + (tn << 2)) = o1;
        }
    }
}

// ---------------- kernel 2: persistent RNN recurrence -----------------------
// R11 engine.  128 CTAs: blockIdx = rg*8 + cg.  128 threads/CTA.
// Thread tile: 8 rows x 8 cols x 64 K (kq in [0,8) splits K).
// New in R12: hardware tanh; own 16x64 h-block written directly to smem after
// the publish barrier (staging skips own chunk -> less L2 traffic + latency).
__global__ __launch_bounds__(RNN_THREADS, 1) void rnn_recur(
    const int*   __restrict__ x,    // [256][512] tokens
    const float* __restrict__ Wh)   // [512][512]
{
    extern __shared__ float smem[];
    float* wt = smem;                 // [64][CSTR] rotated transpose
    float* hs = smem + 64 * CSTR;     // [16][CSTR] linear, cols = global d

    const int tid  = threadIdx.x;
    const int warp = tid >> 5;
    const int lane = tid & 31;
    const int rg   = blockIdx.x >> 3;
    const int cg   = blockIdx.x & 7;
    const int col0 = cg * 64;
    const int row0 = rg * 16;

    // one-time rotated transposed load:
    // wt[c][ ((d>>2 + 2*(c>>3)) & 127)*4 + (d&3) ] = Wh[d][col0+c]
    for (int idx = tid; idx < 512 * 16; idx += RNN_THREADS) {
        int d  = idx >> 4;
        int c4 = (idx & 15) << 2;
        int f  = d >> 2;
        int dl = d & 3;
        float4 v = *(const float4*)(Wh + (size_t)d * DIM + col0 + c4);
        float vv[4] = {v.x, v.y, v.z, v.w};
        #pragma unroll
        for (int q = 0; q < 4; q++) {
            int c = c4 + q;
            int p = (f + 2 * (c >> 3)) & 127;
            wt[c * CSTR + (p << 2) + dl] = vv[q];
        }
    }

    // thread mapping (R7/R11)
    const int kq   = lane & 7;                 // K-slice 0..7 (64 d each)
    const int cqlo = lane >> 3;                // 0..3
    const int cq   = ((warp & 1) << 2) | cqlo; // 0..7  -> 8 cols each
    const int rq   = warp >> 1;                // 0..1  -> 8 rows each
    const int c0   = cq << 3;                  // col in [0,64)
    const int r0   = rq << 3;                  // row in [0,16)
    const int rot  = 2 * cq;                   // wt rotation for these cols

    const int outrow  = row0 + r0 + kq;        // this thread's output row
    const int outrloc = r0 + kq;               // local row in hs
    const int outcolg = col0 + c0;             // global col base (8 cols)
    const int* xrow = x + (size_t)outrow * SEQL;

    // staging role: thread stages column-float4 index == tid, 16 rows deep.
    // threads whose column falls in this CTA's own 64-col chunk skip staging.
    const bool stager = ((tid >> 4) != cg);

    unsigned* myflag = &g_flags[rg][cg];
    const unsigned base = ldflag_acq(myflag);  // replay-safe monotonic base

    __syncthreads();

    for (int l = 0; l < SEQL; l++) {
        // prefetch xin early (independent of sync / h)
        int token = __ldg(xrow + l);
        const float* embrow = g_embW + (size_t)token * DIM + outcolg;
        float4 xin0 = __ldg((const float4*)embrow);
        float4 xin1 = __ldg((const float4*)(embrow + 4));

        float fin[8];
        #pragma unroll
        for (int i = 0; i < 8; i++) fin[i] = 0.f;

        if (l > 0) {
            // ---- per-group acquire wait (7 remote producers; own chunk local) ----
            unsigned target = base + (unsigned)l;
            if (lane < 8 && lane != cg) {
                const unsigned* f = &g_flags[rg][lane];
                while ((int)(ldflag_acq(f) - target) < 0) { }
            }
            __syncwarp();   // ordering bridge to non-polling lanes

            // ---- stage 16x448 sibling h data (28KB) from L2, deep MLP ----
            if (stager) {
                const float4* src = (const float4*)(g_h
                    + (size_t)(l & 1) * (BATCH * DIM) + (size_t)row0 * DIM) + tid;
                float4* dst = (float4*)(hs) + tid;
                #pragma unroll
                for (int k = 0; k < 16; k++)
                    dst[k * (CSTR / 4)] = __ldcg(src + k * (DIM / 4));
            }
            __syncthreads();

            // ---- h @ Wh: 8 rows x 8 cols x 64 K, fp32x2 packed over K ----
            ull acc[8][8];
            #pragma unroll
            for (int j = 0; j < 8; j++)
                #pragma unroll
                for (int i = 0; i < 8; i++) acc[j][i] = 0ull;

            const float* wbase = wt + c0 * CSTR;

            #pragma unroll 4
            for (int dq = 0; dq < 16; dq++) {
                int s   = (dq + kq) & 15;
                int di  = (kq << 4) + s;           // natural float4 index (hv)
                int dr  = (di + rot) & 127;        // rotated float4 index (wv)
                int dbh = di << 2;
                int dbw = dr << 2;

                ulonglong2 wv[8];
                #pragma unroll
                for (int i = 0; i < 8; i++)
                    wv[i] = *(const ulonglong2*)(wbase + i * CSTR + dbw);

                #pragma unroll
                for (int j = 0; j < 8; j++) {
                    ulonglong2 hv = *(const ulonglong2*)(hs + (r0 + j) * CSTR + dbh);
                    #pragma unroll
                    for (int i = 0; i < 8; i++) {
                        acc[j][i] = fma2(hv.x, wv[i].x, acc[j][i]);
                        acc[j][i] = fma2(hv.y, wv[i].y, acc[j][i]);
                    }
                }
            }

            // ---- reduce-scatter over 8 kq lanes (rounds xor 4,2,1) ----
            #pragma unroll
            for (int i = 0; i < 8; i++) {
                #pragma unroll
                for (int jj = 0; jj < 4; jj++) {
                    ull s = (kq & 4) ? acc[jj][i] : acc[jj + 4][i];
                    ull r = shflx64(s, 4);
                    ull kkeep = (kq & 4) ? acc[jj + 4][i] : acc[jj][i];
                    acc[jj][i] = add2(kkeep, r);
                }
                #pragma unroll
                for (int jj = 0; jj < 2; jj++) {
                    ull s = (kq & 2) ? acc[jj][i] : acc[jj + 2][i];
                    ull r = shflx64(s, 2);
                    ull kkeep = (kq & 2) ? acc[jj + 2][i] : acc[jj][i];
                    acc[jj][i] = add2(kkeep, r);
                }
                {
                    ull s = (kq & 1) ? acc[0][i] : acc[1][i];
                    ull r = shflx64(s, 1);
                    ull kkeep = (kq & 1) ? acc[1][i] : acc[0][i];
                    ull f = add2(kkeep, r);
                    float2 ff = *(float2*)&f;
                    fin[i] = ff.x + ff.y;    // horizontal add of the K pair streams
                }
            }
        }

        float4 hn0, hn1;
        hn0.x = tanhfast(fin[0] + xin0.x);
        hn0.y = tanhfast(fin[1] + xin0.y);
        hn0.z = tanhfast(fin[2] + xin0.z);
        hn0.w = tanhfast(fin[3] + xin0.w);
        hn1.x = tanhfast(fin[4] + xin1.x);
        hn1.y = tanhfast(fin[5] + xin1.y);
        hn1.z = tanhfast(fin[6] + xin1.z);
        hn1.w = tanhfast(fin[7] + xin1.w);

        float* hdst = g_h + (size_t)((l + 1) & 1) * (BATCH * DIM)
                          + (size_t)outrow * DIM + outcolg;
        __stcg((float4*)hdst,       hn0);
        __stcg((float4*)(hdst + 4), hn1);

        // ---- publish: CTA barrier (cta-scope fence) then release store ----
        __syncthreads();
        if (tid == 0) stflag_rel(myflag, base + (unsigned)(l + 1));

        // own 16x64 block into hs for next step (race-free: next staging
        // __syncthreads orders these writes before any cross-thread read;
        // staging never touches this CTA's own column range)
        *(float4*)&hs[outrloc * CSTR + outcolg]     = hn0;
        *(float4*)&hs[outrloc * CSTR + outcolg + 4] = hn1;
    }
    // flags end at base+512: next launch re-reads as its new base (no reset)
}

// ---------------- kernel 3: logits + softmax --------------------------------
__global__ __launch_bounds__(256) void softmax_kernel(
    const float* __restrict__ Wd,   // [512][20]
    const float* __restrict__ bd,   // [20]
    float* __restrict__ out)        // [256][20]
{
    int b    = blockIdx.x * 8 + (threadIdx.x >> 5);
    int lane = threadIdx.x & 31;
    if (b >= BATCH) return;

    const float* h = g_h + (size_t)b * DIM;

    float acc[NCLS];
    #pragma unroll
    for (int c = 0; c < NCLS; c++) acc[c] = 0.f;

    for (int d = lane; d < DIM; d += 32) {
        float hv = __ldcg(h + d);
        #pragma unroll
        for (int c = 0; c < NCLS; c++)
            acc[c] += hv * Wd[d * NCLS + c];
    }
    #pragma unroll
    for (int c = 0; c < NCLS; c++) {
        #pragma unroll
        for (int off = 16; off > 0; off >>= 1)
            acc[c] += __shfl_xor_sync(0xFFFFFFFFu, acc[c], off);
    }
    if (lane == 0) {
        float logit[NCLS];
        float m = -1e30f;
        #pragma unroll
        for (int c = 0; c < NCLS; c++) {
            logit[c] = acc[c] + bd[c];
            m = fmaxf(m, logit[c]);
        }
        float s = 0.f;
        #pragma unroll
        for (int c = 0; c < NCLS; c++) {
            logit[c] = expf(logit[c] - m);
            s += logit[c];
        }
        float inv = 1.0f / s;
        #pragma unroll
        for (int c = 0; c < NCLS; c++)
            out[b * NCLS + c] = logit[c] * inv;
    }
}

// ---------------- launch ----------------------------------------------------
extern "C" void kernel_launch(void* const* d_in, const int* in_sizes, int n_in,
                              void* d_out, int out_size)
{
    const int*   x   = (const int*)  d_in[0];
    const float* emb = (const float*)d_in[1];
    const float* Wx  = (const float*)d_in[2];
    const float* Wh  = (const float*)d_in[3];
    const float* b   = (const float*)d_in[4];
    const float* Wd  = (const float*)d_in[5];
    const float* bd  = (const float*)d_in[6];
    float* out = (float*)d_out;

    // 1) embW = emb @ Wx + b
    embw_gemm<<<dim3(DIM / 128, (VOCAB + 127) / 128), 256>>>(emb, Wx, b, VOCAB);

    // 2) persistent recurrence (128 CTAs x 128 threads, ~165KB smem, all resident)
    cudaFuncSetAttribute(rnn_recur, cudaFuncAttributeMaxDynamicSharedMemorySize,
                         RNN_SMEM_BYTES);
    rnn_recur<<<128, RNN_THREADS, RNN_SMEM_BYTES>>>(x, Wh);

    // 3) logits + softmax
    softmax_kernel<<<(BATCH + 7) / 8, 256>>>(Wd, bd, out);
}

// round 14
// speedup vs baseline: 1.0183x; 1.0183x over previous
#include <cuda_runtime.h>
#include <cuda_bf16.h>
#include <math.h>

// Problem constants
#define VOCAB 50000
#define DIM   512
#define SEQL  512
#define BATCH 256
#define NCLS  20

// smem layout (floats): wt[64][516] rotated+transposed Wh slice, hs[16][516]
#define CSTR  516
#define RNN_SMEM_FLOATS ((64 + 16) * CSTR)
#define RNN_SMEM_BYTES  (RNN_SMEM_FLOATS * 4)   // 165,120 B
#define RNN_THREADS 128

typedef unsigned long long ull;

// ---------------- device scratch (no runtime alloc allowed) ----------------
__device__ float g_embW[(size_t)VOCAB * DIM];       // emb @ Wx + b, ~100 MB
__device__ float g_h[2 * BATCH * DIM];              // ping-pong hidden state
// step flags: 32B stride -> each flag in its own L2 sector (no LTS serialization)
__device__ unsigned g_flags[16][64];                // flag at [rg][cg*8]

// strong acquire/release flag ops (R7/R11-proven protocol)
__device__ __forceinline__ unsigned ldflag_acq(const unsigned* p) {
    unsigned v;
    asm volatile("ld.acquire.gpu.global.u32 %0, [%1];" : "=r"(v) : "l"(p) : "memory");
    return v;
}
__device__ __forceinline__ void stflag_rel(unsigned* p, unsigned v) {
    asm volatile("st.release.gpu.global.u32 [%0], %1;" :: "l"(p), "r"(v) : "memory");
}

// hardware tanh (MUFU.TANH) — R13-validated: final rel_err 2.4e-6
__device__ __forceinline__ float tanhfast(float x) {
    float y;
    asm("tanh.approx.f32 %0, %1;" : "=f"(y) : "f"(x));
    return y;
}

// packed fp32x2 math (sm_103a native; ptxas never auto-generates these)
__device__ __forceinline__ ull fma2(ull a, ull b, ull c) {
    ull d;
    asm("fma.rn.f32x2 %0, %1, %2, %3;" : "=l"(d) : "l"(a), "l"(b), "l"(c));
    return d;
}
__device__ __forceinline__ ull add2(ull a, ull b) {
    ull d;
    asm("add.rn.f32x2 %0, %1, %2;" : "=l"(d) : "l"(a), "l"(b));
    return d;
}
__device__ __forceinline__ ull pack2(float v) {
    ull d;
    asm("mov.b64 %0, {%1, %2};" : "=l"(d) : "f"(v), "f"(v));
    return d;
}
__device__ __forceinline__ ull shflx64(ull v, int m) {
    unsigned lo = (unsigned)v, hi = (unsigned)(v >> 32);
    lo = __shfl_xor_sync(0xffffffffu, lo, m);
    hi = __shfl_xor_sync(0xffffffffu, hi, m);
    return ((ull)hi << 32) | (ull)lo;
}

// ---------------- kernel 1: embW = emb @ Wx + b  (fp32x2 tiled GEMM) --------
// BM=128, BN=128, BK=16, 256 threads, 8x8 per thread; accumulate in fp32x2
// pairs along N (halves FFMA issue slots; packs dual-issue on alu pipe).
__global__ __launch_bounds__(256, 2) void embw_gemm(
    const float* __restrict__ A,    // emb [M][512]
    const float* __restrict__ B,    // Wx  [512][512]
    const float* __restrict__ bias, // b [512]
    int M)
{
    __shared__ float As[16][132];   // transposed A tile [k][m], padded
    __shared__ float Bs[16][128];   // [k][n]

    const int tid  = threadIdx.x;
    const int row0 = blockIdx.y * 128;
    const int col0 = blockIdx.x * 128;
    const int tm = tid >> 4;        // 0..15 -> 8 rows each
    const int tn = tid & 15;        // 0..15 -> cols tn*4 and 64+tn*4

    ull acc0[8][2], acc1[8][2];     // [row][colpair] fp32x2 accumulators
    #pragma unroll
    for (int i = 0; i < 8; i++) {
        acc0[i][0] = 0ull; acc0[i][1] = 0ull;
        acc1[i][0] = 0ull; acc1[i][1] = 0ull;
    }

    for (int k0 = 0; k0 < DIM; k0 += 16) {
        #pragma unroll
        for (int t = 0; t < 2; t++) {
            int idx = tid + t * 256;
            int am  = idx >> 2;
            int ak4 = (idx & 3) << 2;
            float4 av = make_float4(0.f, 0.f, 0.f, 0.f);
            if (row0 + am < M)
                av = *(const float4*)(A + (size_t)(row0 + am) * DIM + k0 + ak4);
            As[ak4 + 0][am] = av.x;
            As[ak4 + 1][am] = av.y;
            As[ak4 + 2][am] = av.z;
            As[ak4 + 3][am] = av.w;
        }
        #pragma unroll
        for (int t = 0; t < 2; t++) {
            int idx = tid + t * 256;
            int bk  = idx >> 5;
            int bn4 = (idx & 31) << 2;
            *(float4*)&Bs[bk][bn4] =
                *(const float4*)(B + (size_t)(k0 + bk) * DIM + col0 + bn4);
        }
        __syncthreads();

        #pragma unroll
        for (int kk = 0; kk < 16; kk++) {
            ulonglong2 b0 = *(const ulonglong2*)&Bs[kk][tn << 2];
            ulonglong2 b1 = *(const ulonglong2*)&Bs[kk][64 + (tn << 2)];
            float4 a0 = *(const float4*)&As[kk][tm * 8];
            float4 a1 = *(const float4*)&As[kk][tm * 8 + 4];
            float av[8] = {a0.x, a0.y, a0.z, a0.w, a1.x, a1.y, a1.z, a1.w};
            #pragma unroll
            for (int i = 0; i < 8; i++) {
                ull ad = pack2(av[i]);
                acc0[i][0] = fma2(ad, b0.x, acc0[i][0]);
                acc0[i][1] = fma2(ad, b0.y, acc0[i][1]);
                acc1[i][0] = fma2(ad, b1.x, acc1[i][0]);
                acc1[i][1] = fma2(ad, b1.y, acc1[i][1]);
            }
        }
        __syncthreads();
    }

    float4 bb0 = *(const float4*)(bias + col0 + (tn << 2));
    float4 bb1 = *(const float4*)(bias + col0 + 64 + (tn << 2));
    #pragma unroll
    for (int i = 0; i < 8; i++) {
        int row = row0 + tm * 8 + i;
        if (row < M) {
            float2 p00 = *(float2*)&acc0[i][0];
            float2 p01 = *(float2*)&acc0[i][1];
            float2 p10 = *(float2*)&acc1[i][0];
            float2 p11 = *(float2*)&acc1[i][1];
            float4 o0, o1;
            o0.x = p00.x + bb0.x; o0.y = p00.y + bb0.y;
            o0.z = p01.x + bb0.z; o0.w = p01.y + bb0.w;
            o1.x = p10.x + bb1.x; o1.y = p10.y + bb1.y;
            o1.z = p11.x + bb1.z; o1.w = p11.y + bb1.w;
            *(float4*)(g_embW + (size_t)row * DIM + col0 + (tn << 2))      = o0;
            *(float4*)(g_embW + (size_t)row * DIM + col0 + 64 + (tn << 2)) = o1;
        }
    }
}

// ---------------- kernel 2: persistent RNN recurrence -----------------------
// R13 engine verbatim (best measured), flags now sector-padded.
__global__ __launch_bounds__(RNN_THREADS, 1) void rnn_recur(
    const int*   __restrict__ x,    // [256][512] tokens
    const float* __restrict__ Wh)   // [512][512]
{
    extern __shared__ float smem[];
    float* wt = smem;                 // [64][CSTR] rotated transpose
    float* hs = smem + 64 * CSTR;     // [16][CSTR] linear, cols = global d

    const int tid  = threadIdx.x;
    const int warp = tid >> 5;
    const int lane = tid & 31;
    const int rg   = blockIdx.x >> 3;
    const int cg   = blockIdx.x & 7;
    const int col0 = cg * 64;
    const int row0 = rg * 16;

    // one-time rotated transposed load:
    // wt[c][ ((d>>2 + 2*(c>>3)) & 127)*4 + (d&3) ] = Wh[d][col0+c]
    for (int idx = tid; idx < 512 * 16; idx += RNN_THREADS) {
        int d  = idx >> 4;
        int c4 = (idx & 15) << 2;
        int f  = d >> 2;
        int dl = d & 3;
        float4 v = *(const float4*)(Wh + (size_t)d * DIM + col0 + c4);
        float vv[4] = {v.x, v.y, v.z, v.w};
        #pragma unroll
        for (int q = 0; q < 4; q++) {
            int c = c4 + q;
            int p = (f + 2 * (c >> 3)) & 127;
            wt[c * CSTR + (p << 2) + dl] = vv[q];
        }
    }

    // thread mapping (R7/R11)
    const int kq   = lane & 7;                 // K-slice 0..7 (64 d each)
    const int cqlo = lane >> 3;                // 0..3
    const int cq   = ((warp & 1) << 2) | cqlo; // 0..7  -> 8 cols each
    const int rq   = warp >> 1;                // 0..1  -> 8 rows each
    const int c0   = cq << 3;                  // col in [0,64)
    const int r0   = rq << 3;                  // row in [0,16)
    const int rot  = 2 * cq;                   // wt rotation for these cols

    const int outrow  = row0 + r0 + kq;        // this thread's output row
    const int outrloc = r0 + kq;               // local row in hs
    const int outcolg = col0 + c0;             // global col base (8 cols)
    const int* xrow = x + (size_t)outrow * SEQL;

    // staging role: thread stages column-float4 index == tid, 16 rows deep.
    // threads whose column falls in this CTA's own 64-col chunk skip staging.
    const bool stager = ((tid >> 4) != cg);

    unsigned* myflag = &g_flags[rg][cg << 3];
    const unsigned base = ldflag_acq(myflag);  // replay-safe monotonic base

    __syncthreads();

    for (int l = 0; l < SEQL; l++) {
        // prefetch xin early (independent of sync / h)
        int token = __ldg(xrow + l);
        const float* embrow = g_embW + (size_t)token * DIM + outcolg;
        float4 xin0 = __ldg((const float4*)embrow);
        float4 xin1 = __ldg((const float4*)(embrow + 4));

        float fin[8];
        #pragma unroll
        for (int i = 0; i < 8; i++) fin[i] = 0.f;

        if (l > 0) {
            // ---- per-group acquire wait (7 remote producers; own chunk local) ----
            unsigned target = base + (unsigned)l;
            if (lane < 8 && lane != cg) {
                const unsigned* f = &g_flags[rg][lane << 3];
                while ((int)(ldflag_acq(f) - target) < 0) { }
            }
            __syncwarp();   // ordering bridge to non-polling lanes

            // ---- stage 16x448 sibling h data (28KB) from L2, deep MLP ----
            if (stager) {
                const float4* src = (const float4*)(g_h
                    + (size_t)(l & 1) * (BATCH * DIM) + (size_t)row0 * DIM) + tid;
                float4* dst = (float4*)(hs) + tid;
                #pragma unroll
                for (int k = 0; k < 16; k++)
                    dst[k * (CSTR / 4)] = __ldcg(src + k * (DIM / 4));
            }
            __syncthreads();

            // ---- h @ Wh: 8 rows x 8 cols x 64 K, fp32x2 packed over K ----
            ull acc[8][8];
            #pragma unroll
            for (int j = 0; j < 8; j++)
                #pragma unroll
                for (int i = 0; i < 8; i++) acc[j][i] = 0ull;

            const float* wbase = wt + c0 * CSTR;

            #pragma unroll 4
            for (int dq = 0; dq < 16; dq++) {
                int s   = (dq + kq) & 15;
                int di  = (kq << 4) + s;           // natural float4 index (hv)
                int dr  = (di + rot) & 127;        // rotated float4 index (wv)
                int dbh = di << 2;
                int dbw = dr << 2;

                ulonglong2 wv[8];
                #pragma unroll
                for (int i = 0; i < 8; i++)
                    wv[i] = *(const ulonglong2*)(wbase + i * CSTR + dbw);

                #pragma unroll
                for (int j = 0; j < 8; j++) {
                    ulonglong2 hv = *(const ulonglong2*)(hs + (r0 + j) * CSTR + dbh);
                    #pragma unroll
                    for (int i = 0; i < 8; i++) {
                        acc[j][i] = fma2(hv.x, wv[i].x, acc[j][i]);
                        acc[j][i] = fma2(hv.y, wv[i].y, acc[j][i]);
                    }
                }
            }

            // ---- reduce-scatter over 8 kq lanes (rounds xor 4,2,1) ----
            #pragma unroll
            for (int i = 0; i < 8; i++) {
                #pragma unroll
                for (int jj = 0; jj < 4; jj++) {
                    ull s = (kq & 4) ? acc[jj][i] : acc[jj + 4][i];
                    ull r = shflx64(s, 4);
                    ull kkeep = (kq & 4) ? acc[jj + 4][i] : acc[jj][i];
                    acc[jj][i] = add2(kkeep, r);
                }
                #pragma unroll
                for (int jj = 0; jj < 2; jj++) {
                    ull s = (kq & 2) ? acc[jj][i] : acc[jj + 2][i];
                    ull r = shflx64(s, 2);
                    ull kkeep = (kq & 2) ? acc[jj + 2][i] : acc[jj][i];
                    acc[jj][i] = add2(kkeep, r);
                }
                {
                    ull s = (kq & 1) ? acc[0][i] : acc[1][i];
                    ull r = shflx64(s, 1);
                    ull kkeep = (kq & 1) ? acc[1][i] : acc[0][i];
                    ull f = add2(kkeep, r);
                    float2 ff = *(float2*)&f;
                    fin[i] = ff.x + ff.y;    // horizontal add of the K pair streams
                }
            }
        }

        float4 hn0, hn1;
        hn0.x = tanhfast(fin[0] + xin0.x);
        hn0.y = tanhfast(fin[1] + xin0.y);
        hn0.z = tanhfast(fin[2] + xin0.z);
        hn0.w = tanhfast(fin[3] + xin0.w);
        hn1.x = tanhfast(fin[4] + xin1.x);
        hn1.y = tanhfast(fin[5] + xin1.y);
        hn1.z = tanhfast(fin[6] + xin1.z);
        hn1.w = tanhfast(fin[7] + xin1.w);

        float* hdst = g_h + (size_t)((l + 1) & 1) * (BATCH * DIM)
                          + (size_t)outrow * DIM + outcolg;
        __stcg((float4*)hdst,       hn0);
        __stcg((float4*)(hdst + 4), hn1);

        // ---- publish: CTA barrier (cta-scope fence) then release store ----
        __syncthreads();
        if (tid == 0) stflag_rel(myflag, base + (unsigned)(l + 1));

        // own 16x64 block into hs for next step (race-free: next staging
        // __syncthreads orders these writes before any cross-thread read;
        // staging never touches this CTA's own column range)
        *(float4*)&hs[outrloc * CSTR + outcolg]     = hn0;
        *(float4*)&hs[outrloc * CSTR + outcolg + 4] = hn1;
    }
    // flags end at base+512: next launch re-reads as its new base (no reset)
}

// ---------------- kernel 3: logits + softmax --------------------------------
__global__ __launch_bounds__(256) void softmax_kernel(
    const float* __restrict__ Wd,   // [512][20]
    const float* __restrict__ bd,   // [20]
    float* __restrict__ out)        // [256][20]
{
    int b    = blockIdx.x * 8 + (threadIdx.x >> 5);
    int lane = threadIdx.x & 31;
    if (b >= BATCH) return;

    const float* h = g_h + (size_t)b * DIM;

    float acc[NCLS];
    #pragma unroll
    for (int c = 0; c < NCLS; c++) acc[c] = 0.f;

    for (int d = lane; d < DIM; d += 32) {
        float hv = __ldcg(h + d);
        #pragma unroll
        for (int c = 0; c < NCLS; c++)
            acc[c] += hv * Wd[d * NCLS + c];
    }
    #pragma unroll
    for (int c = 0; c < NCLS; c++) {
        #pragma unroll
        for (int off = 16; off > 0; off >>= 1)
            acc[c] += __shfl_xor_sync(0xFFFFFFFFu, acc[c], off);
    }
    if (lane == 0) {
        float logit[NCLS];
        float m = -1e30f;
        #pragma unroll
        for (int c = 0; c < NCLS; c++) {
            logit[c] = acc[c] + bd[c];
            m = fmaxf(m, logit[c]);
        }
        float s = 0.f;
        #pragma unroll
        for (int c = 0; c < NCLS; c++) {
            logit[c] = expf(logit[c] - m);
            s += logit[c];
        }
        float inv = 1.0f / s;
        #pragma unroll
        for (int c = 0; c < NCLS; c++)
            out[b * NCLS + c] = logit[c] * inv;
    }
}

// ---------------- launch ----------------------------------------------------
extern "C" void kernel_launch(void* const* d_in, const int* in_sizes, int n_in,
                              void* d_out, int out_size)
{
    const int*   x   = (const int*)  d_in[0];
    const float* emb = (const float*)d_in[1];
    const float* Wx  = (const float*)d_in[2];
    const float* Wh  = (const float*)d_in[3];
    const float* b   = (const float*)d_in[4];
    const float* Wd  = (const float*)d_in[5];
    const float* bd  = (const float*)d_in[6];
    float* out = (float*)d_out;

    // 1) embW = emb @ Wx + b
    embw_gemm<<<dim3(DIM / 128, (VOCAB + 127) / 128), 256>>>(emb, Wx, b, VOCAB);

    // 2) persistent recurrence (128 CTAs x 128 threads, ~165KB smem, all resident)
    cudaFuncSetAttribute(rnn_recur, cudaFuncAttributeMaxDynamicSharedMemorySize,
                         RNN_SMEM_BYTES);
    rnn_recur<<<128, RNN_THREADS, RNN_SMEM_BYTES>>>(x, Wh);

    // 3) logits + softmax
    softmax_kernel<<<(BATCH + 7) / 8, 256>>>(Wd, bd, out);
}

// round 15
// speedup vs baseline: 1.5666x; 1.5385x over previous
#include <cuda_runtime.h>
#include <cuda_bf16.h>
#include <math.h>

// Problem constants
#define VOCAB 50000
#define DIM   512
#define SEQL  512
#define BATCH 256
#define NCLS  20

// smem layout (floats): wt[64][516] transposed tf32 Wh slice, hs[16][516]
#define CSTR  516
#define RNN_SMEM_FLOATS ((64 + 16) * CSTR)
#define RNN_SMEM_BYTES  (RNN_SMEM_FLOATS * 4)   // 165,120 B
#define RNN_THREADS 128

typedef unsigned long long ull;

// ---------------- device scratch (no runtime alloc allowed) ----------------
__device__ float g_embW[(size_t)VOCAB * DIM];       // emb @ Wx + b, ~100 MB
__device__ float g_h[2 * BATCH * DIM];              // ping-pong hidden state (tf32-rounded)
// step flags: 32B stride -> each flag in its own L2 sector
__device__ unsigned g_flags[16][64];                // flag at [rg][cg*8]

// strong acquire/release flag ops (R7/R11-proven protocol)
__device__ __forceinline__ unsigned ldflag_acq(const unsigned* p) {
    unsigned v;
    asm volatile("ld.acquire.gpu.global.u32 %0, [%1];" : "=r"(v) : "l"(p) : "memory");
    return v;
}
__device__ __forceinline__ void stflag_rel(unsigned* p, unsigned v) {
    asm volatile("st.release.gpu.global.u32 [%0], %1;" :: "l"(p), "r"(v) : "memory");
}

// hardware tanh (MUFU.TANH) — R13-validated: final rel_err 2.4e-6
__device__ __forceinline__ float tanhfast(float x) {
    float y;
    asm("tanh.approx.f32 %0, %1;" : "=f"(y) : "f"(x));
    return y;
}

// round fp32 -> tf32 bit pattern (rna), returned as fp32 value
__device__ __forceinline__ float tf32r(float f) {
    unsigned u;
    asm("cvt.rna.tf32.f32 %0, %1;" : "=r"(u) : "f"(f));
    return __uint_as_float(u);
}

// m16n8k8 TF32 tensor mma, fp32 accumulate (register fragments)
__device__ __forceinline__ void mma_tf32(float c[4],
    unsigned a0, unsigned a1, unsigned a2, unsigned a3,
    unsigned b0, unsigned b1)
{
    asm("mma.sync.aligned.m16n8k8.row.col.f32.tf32.tf32.f32 "
        "{%0,%1,%2,%3}, {%4,%5,%6,%7}, {%8,%9}, {%0,%1,%2,%3};"
        : "+f"(c[0]), "+f"(c[1]), "+f"(c[2]), "+f"(c[3])
        : "r"(a0), "r"(a1), "r"(a2), "r"(a3), "r"(b0), "r"(b1));
}

// packed fp32x2 math for embw_gemm (R14-proven)
__device__ __forceinline__ ull fma2(ull a, ull b, ull c) {
    ull d;
    asm("fma.rn.f32x2 %0, %1, %2, %3;" : "=l"(d) : "l"(a), "l"(b), "l"(c));
    return d;
}
__device__ __forceinline__ ull pack2(float v) {
    ull d;
    asm("mov.b64 %0, {%1, %2};" : "=l"(d) : "f"(v), "f"(v));
    return d;
}

// ---------------- kernel 1: embW = emb @ Wx + b  (fp32x2 tiled GEMM) --------
__global__ __launch_bounds__(256, 2) void embw_gemm(
    const float* __restrict__ A,    // emb [M][512]
    const float* __restrict__ B,    // Wx  [512][512]
    const float* __restrict__ bias, // b [512]
    int M)
{
    __shared__ float As[16][132];   // transposed A tile [k][m], padded
    __shared__ float Bs[16][128];   // [k][n]

    const int tid  = threadIdx.x;
    const int row0 = blockIdx.y * 128;
    const int col0 = blockIdx.x * 128;
    const int tm = tid >> 4;
    const int tn = tid & 15;

    ull acc0[8][2], acc1[8][2];
    #pragma unroll
    for (int i = 0; i < 8; i++) {
        acc0[i][0] = 0ull; acc0[i][1] = 0ull;
        acc1[i][0] = 0ull; acc1[i][1] = 0ull;
    }

    for (int k0 = 0; k0 < DIM; k0 += 16) {
        #pragma unroll
        for (int t = 0; t < 2; t++) {
            int idx = tid + t * 256;
            int am  = idx >> 2;
            int ak4 = (idx & 3) << 2;
            float4 av = make_float4(0.f, 0.f, 0.f, 0.f);
            if (row0 + am < M)
                av = *(const float4*)(A + (size_t)(row0 + am) * DIM + k0 + ak4);
            As[ak4 + 0][am] = av.x;
            As[ak4 + 1][am] = av.y;
            As[ak4 + 2][am] = av.z;
            As[ak4 + 3][am] = av.w;
        }
        #pragma unroll
        for (int t = 0; t < 2; t++) {
            int idx = tid + t * 256;
            int bk  = idx >> 5;
            int bn4 = (idx & 31) << 2;
            *(float4*)&Bs[bk][bn4] =
                *(const float4*)(B + (size_t)(k0 + bk) * DIM + col0 + bn4);
        }
        __syncthreads();

        #pragma unroll
        for (int kk = 0; kk < 16; kk++) {
            ulonglong2 b0 = *(const ulonglong2*)&Bs[kk][tn << 2];
            ulonglong2 b1 = *(const ulonglong2*)&Bs[kk][64 + (tn << 2)];
            float4 a0 = *(const float4*)&As[kk][tm * 8];
            float4 a1 = *(const float4*)&As[kk][tm * 8 + 4];
            float av[8] = {a0.x, a0.y, a0.z, a0.w, a1.x, a1.y, a1.z, a1.w};
            #pragma unroll
            for (int i = 0; i < 8; i++) {
                ull ad = pack2(av[i]);
                acc0[i][0] = fma2(ad, b0.x, acc0[i][0]);
                acc0[i][1] = fma2(ad, b0.y, acc0[i][1]);
                acc1[i][0] = fma2(ad, b1.x, acc1[i][0]);
                acc1[i][1] = fma2(ad, b1.y, acc1[i][1]);
            }
        }
        __syncthreads();
    }

    float4 bb0 = *(const float4*)(bias + col0 + (tn << 2));
    float4 bb1 = *(const float4*)(bias + col0 + 64 + (tn << 2));
    #pragma unroll
    for (int i = 0; i < 8; i++) {
        int row = row0 + tm * 8 + i;
        if (row < M) {
            float2 p00 = *(float2*)&acc0[i][0];
            float2 p01 = *(float2*)&acc0[i][1];
            float2 p10 = *(float2*)&acc1[i][0];
            float2 p11 = *(float2*)&acc1[i][1];
            float4 o0, o1;
            o0.x = p00.x + bb0.x; o0.y = p00.y + bb0.y;
            o0.z = p01.x + bb0.z; o0.w = p01.y + bb0.w;
            o1.x = p10.x + bb1.x; o1.y = p10.y + bb1.y;
            o1.z = p11.x + bb1.z; o1.w = p11.y + bb1.w;
            *(float4*)(g_embW + (size_t)row * DIM + col0 + (tn << 2))      = o0;
            *(float4*)(g_embW + (size_t)row * DIM + col0 + 64 + (tn << 2)) = o1;
        }
    }
}

// ---------------- kernel 2: persistent RNN recurrence (TF32 tensor) ---------
// 128 CTAs: blockIdx = rg*8 + cg.  128 threads/CTA, 4 warps.
// Warp w computes all 16 rows x cols [16w,16w+16) via m16n8k8 tf32 mma
// (2 n-tiles, 64 k-iters, fp32 accumulators seeded with xin).
// Fragment map (PTX): g=lane>>2, t=lane&3.
//   A: a0=(g,t) a1=(g+8,t) a2=(g,t+4) a3=(g+8,t+4)   [rows=h batch, cols=k]
//   B: b0=(k=t, n=g) b1=(k=t+4, n=g)                  [from wt transposed]
//   D: c0=(g,2t) c1=(g,2t+1) c2=(g+8,2t) c3=(g+8,2t+1)
// CSTR=516 pad makes all A/B scalar LDS conflict-free (word bank = 4g+t+k0).
// Sync fabric: R11/R14 proven (sector-padded flags, bar.sync + st.release;
// eager per-chunk poll by staging threads).
__global__ __launch_bounds__(RNN_THREADS, 1) void rnn_recur(
    const int*   __restrict__ x,    // [256][512] tokens
    const float* __restrict__ Wh)   // [512][512]
{
    extern __shared__ float smem[];
    float* wt = smem;                 // [64][CSTR]: wt[c][d] = tf32(Wh[d][col0+c])
    float* hs = smem + 64 * CSTR;     // [16][CSTR]: rows=batch-local, cols=global d

    const int tid  = threadIdx.x;
    const int warp = tid >> 5;
    const int lane = tid & 31;
    const int rg   = blockIdx.x >> 3;
    const int cg   = blockIdx.x & 7;
    const int col0 = cg * 64;
    const int row0 = rg * 16;

    // one-time transposed + tf32-rounded Wh slice load
    for (int idx = tid; idx < 512 * 16; idx += RNN_THREADS) {
        int d  = idx >> 4;
        int c4 = (idx & 15) << 2;
        float4 v = *(const float4*)(Wh + (size_t)d * DIM + col0 + c4);
        wt[(c4 + 0) * CSTR + d] = tf32r(v.x);
        wt[(c4 + 1) * CSTR + d] = tf32r(v.y);
        wt[(c4 + 2) * CSTR + d] = tf32r(v.z);
        wt[(c4 + 3) * CSTR + d] = tf32r(v.w);
    }

    // mma thread mapping
    const int g  = lane >> 2;            // fragment group row 0..7
    const int t  = lane & 3;             // thread in group 0..3
    const int nb0 = warp << 4;           // n-tile 0 col base (local 0..63)
    const int nb1 = nb0 + 8;             // n-tile 1

    const int gr0 = row0 + g;            // global batch rows
    const int gr1 = row0 + g + 8;
    const int cga0 = col0 + nb0 + 2 * t; // global col of c0/c1
    const int cga1 = col0 + nb1 + 2 * t; // global col of c4/c5

    // staging role: thread stages float4-column tid of the 16x512 h block,
    // skipping this CTA's own 64-col chunk (tid>>4 == cg)
    const bool stager = ((tid >> 4) != cg);
    const unsigned* mychunkflag = &g_flags[rg][(tid >> 4) << 3];

    unsigned* myflag = &g_flags[rg][cg << 3];
    const unsigned base = ldflag_acq(myflag);  // replay-safe monotonic base

    __syncthreads();

    for (int l = 0; l < SEQL; l++) {
        // prefetch tokens + xin early (independent of sync / h)
        int tok0 = __ldg(x + (size_t)gr0 * SEQL + l);
        int tok1 = __ldg(x + (size_t)gr1 * SEQL + l);
        const float* e0 = g_embW + (size_t)tok0 * DIM;
        const float* e1 = g_embW + (size_t)tok1 * DIM;
        float2 x00 = __ldg((const float2*)(e0 + cga0));
        float2 x01 = __ldg((const float2*)(e0 + cga1));
        float2 x10 = __ldg((const float2*)(e1 + cga0));
        float2 x11 = __ldg((const float2*)(e1 + cga1));

        // accumulators seeded with xin (mma adds h @ Wh on top)
        float c0[4] = {x00.x, x00.y, x10.x, x10.y};
        float c1[4] = {x01.x, x01.y, x11.x, x11.y};

        if (l > 0) {
            // ---- eager staging: poll own source chunk's flag, then stage ----
            if (stager) {
                unsigned target = base + (unsigned)l;
                while ((int)(ldflag_acq(mychunkflag) - target) < 0) { }
                const float4* src = (const float4*)(g_h
                    + (size_t)(l & 1) * (BATCH * DIM) + (size_t)row0 * DIM) + tid;
                float4* dst = (float4*)(hs) + tid;
                #pragma unroll
                for (int k = 0; k < 16; k++)
                    dst[k * (CSTR / 4)] = __ldcg(src + k * (DIM / 4));
            }
            __syncthreads();

            // ---- h @ Wh via tf32 mma: 64 k-iters x 2 n-tiles ----
            const float* hA0 = hs + g * CSTR + t;
            const float* hA1 = hs + (g + 8) * CSTR + t;
            const float* wB0 = wt + (nb0 + g) * CSTR + t;
            const float* wB1 = wt + (nb1 + g) * CSTR + t;

            #pragma unroll 8
            for (int k0 = 0; k0 < DIM; k0 += 8) {
                unsigned a0 = __float_as_uint(hA0[k0]);
                unsigned a1 = __float_as_uint(hA1[k0]);
                unsigned a2 = __float_as_uint(hA0[k0 + 4]);
                unsigned a3 = __float_as_uint(hA1[k0 + 4]);
                unsigned b00 = __float_as_uint(wB0[k0]);
                unsigned b01 = __float_as_uint(wB0[k0 + 4]);
                unsigned b10 = __float_as_uint(wB1[k0]);
                unsigned b11 = __float_as_uint(wB1[k0 + 4]);
                mma_tf32(c0, a0, a1, a2, a3, b00, b01);
                mma_tf32(c1, a0, a1, a2, a3, b10, b11);
            }
        }

        // tanh + tf32 rounding (stored h is exactly representable in tf32)
        float h00 = tf32r(tanhfast(c0[0]));
        float h01 = tf32r(tanhfast(c0[1]));
        float h02 = tf32r(tanhfast(c0[2]));
        float h03 = tf32r(tanhfast(c0[3]));
        float h10 = tf32r(tanhfast(c1[0]));
        float h11 = tf32r(tanhfast(c1[1]));
        float h12 = tf32r(tanhfast(c1[2]));
        float h13 = tf32r(tanhfast(c1[3]));

        float* hbuf = g_h + (size_t)((l + 1) & 1) * (BATCH * DIM);
        __stcg((float2*)(hbuf + (size_t)gr0 * DIM + cga0), make_float2(h00, h01));
        __stcg((float2*)(hbuf + (size_t)gr1 * DIM + cga0), make_float2(h02, h03));
        __stcg((float2*)(hbuf + (size_t)gr0 * DIM + cga1), make_float2(h10, h11));
        __stcg((float2*)(hbuf + (size_t)gr1 * DIM + cga1), make_float2(h12, h13));

        // ---- publish: CTA barrier (cta-scope fence) then release store ----
        __syncthreads();
        if (tid == 0) stflag_rel(myflag, base + (unsigned)(l + 1));

        // own 16x64 block into hs for next step (ordered by next staging barrier)
        *(float2*)&hs[g * CSTR + cga0]       = make_float2(h00, h01);
        *(float2*)&hs[(g + 8) * CSTR + cga0] = make_float2(h02, h03);
        *(float2*)&hs[g * CSTR + cga1]       = make_float2(h10, h11);
        *(float2*)&hs[(g + 8) * CSTR + cga1] = make_float2(h12, h13);
    }
    // flags end at base+512: next launch re-reads as its new base (no reset)
}

// ---------------- kernel 3: logits + softmax --------------------------------
__global__ __launch_bounds__(256) void softmax_kernel(
    const float* __restrict__ Wd,   // [512][20]
    const float* __restrict__ bd,   // [20]
    float* __restrict__ out)        // [256][20]
{
    int b    = blockIdx.x * 8 + (threadIdx.x >> 5);
    int lane = threadIdx.x & 31;
    if (b >= BATCH) return;

    const float* h = g_h + (size_t)b * DIM;

    float acc[NCLS];
    #pragma unroll
    for (int c = 0; c < NCLS; c++) acc[c] = 0.f;

    for (int d = lane; d < DIM; d += 32) {
        float hv = __ldcg(h + d);
        #pragma unroll
        for (int c = 0; c < NCLS; c++)
            acc[c] += hv * Wd[d * NCLS + c];
    }
    #pragma unroll
    for (int c = 0; c < NCLS; c++) {
        #pragma unroll
        for (int off = 16; off > 0; off >>= 1)
            acc[c] += __shfl_xor_sync(0xFFFFFFFFu, acc[c], off);
    }
    if (lane == 0) {
        float logit[NCLS];
        float m = -1e30f;
        #pragma unroll
        for (int c = 0; c < NCLS; c++) {
            logit[c] = acc[c] + bd[c];
            m = fmaxf(m, logit[c]);
        }
        float s = 0.f;
        #pragma unroll
        for (int c = 0; c < NCLS; c++) {
            logit[c] = expf(logit[c] - m);
            s += logit[c];
        }
        float inv = 1.0f / s;
        #pragma unroll
        for (int c = 0; c < NCLS; c++)
            out[b * NCLS + c] = logit[c] * inv;
    }
}

// ---------------- launch ----------------------------------------------------
extern "C" void kernel_launch(void* const* d_in, const int* in_sizes, int n_in,
                              void* d_out, int out_size)
{
    const int*   x   = (const int*)  d_in[0];
    const float* emb = (const float*)d_in[1];
    const float* Wx  = (const float*)d_in[2];
    const float* Wh  = (const float*)d_in[3];
    const float* b   = (const float*)d_in[4];
    const float* Wd  = (const float*)d_in[5];
    const float* bd  = (const float*)d_in[6];
    float* out = (float*)d_out;

    // 1) embW = emb @ Wx + b
    embw_gemm<<<dim3(DIM / 128, (VOCAB + 127) / 128), 256>>>(emb, Wx, b, VOCAB);

    // 2) persistent recurrence (128 CTAs x 128 threads, ~165KB smem, all resident)
    cudaFuncSetAttribute(rnn_recur, cudaFuncAttributeMaxDynamicSharedMemorySize,
                         RNN_SMEM_BYTES);
    rnn_recur<<<128, RNN_THREADS, RNN_SMEM_BYTES>>>(x, Wh);

    // 3) logits + softmax
    softmax_kernel<<<(BATCH + 7) / 8, 256>>>(Wd, bd, out);
}

// round 17
// speedup vs baseline: 1.8380x; 1.1732x over previous
#include <cuda_runtime.h>
#include <cuda_bf16.h>
#include <math.h>

// Problem constants
#define VOCAB 50000
#define DIM   512
#define SEQL  512
#define BATCH 256
#define NCLS  20

#define RNN_THREADS 128
// rnn smem: wtP = 4 warps x 64 k8 x 32 lanes x 4 = 32768 floats; hsP = 8192 floats
#define WTP_FLOATS 32768
#define HSP_FLOATS 8192
#define RNN_SMEM_BYTES ((WTP_FLOATS + HSP_FLOATS) * 4)   // 163,840 B

typedef unsigned long long ull;

// ---------------- device scratch (no runtime alloc allowed) ----------------
__device__ float g_embW[(size_t)VOCAB * DIM];   // emb @ Wx + b (row-major)
// hidden state, PERMUTED fragment layout: [2 bufs][16 row-groups][8192 floats]
__device__ float g_h[2 * BATCH * DIM];
// step flags: 32B stride -> each flag in its own L2 sector
__device__ unsigned g_flags[16][64];            // flag at [rg][cg*8]

// permuted address of h element (r in [0,16), d in [0,512)) within a row-group
// block: fragment order {a0,a1,a2,a3} = {(g,t),(g+8,t),(g,t+4),(g+8,t+4)}
__device__ __forceinline__ int perm_addr(int r, int d) {
    return ((d >> 3) << 7) + ((((r & 7) << 2) + (d & 3)) << 2)
         + (r >> 3) + (((d >> 2) & 1) << 1);
}

// strong acquire/release flag ops (R7/R11-proven protocol)
__device__ __forceinline__ unsigned ldflag_acq(const unsigned* p) {
    unsigned v;
    asm volatile("ld.acquire.gpu.global.u32 %0, [%1];" : "=r"(v) : "l"(p) : "memory");
    return v;
}
__device__ __forceinline__ void stflag_rel(unsigned* p, unsigned v) {
    asm volatile("st.release.gpu.global.u32 [%0], %1;" :: "l"(p), "r"(v) : "memory");
}

// hardware tanh (MUFU.TANH) — R13-validated
__device__ __forceinline__ float tanhfast(float x) {
    float y;
    asm("tanh.approx.f32 %0, %1;" : "=f"(y) : "f"(x));
    return y;
}

// round fp32 -> tf32 (rna), returned as fp32 value
__device__ __forceinline__ float tf32r(float f) {
    unsigned u;
    asm("cvt.rna.tf32.f32 %0, %1;" : "=r"(u) : "f"(f));
    return __uint_as_float(u);
}

// m16n8k8 TF32 tensor mma, fp32 accumulate (R15-validated fragment map)
__device__ __forceinline__ void mma_tf32(float c[4],
    unsigned a0, unsigned a1, unsigned a2, unsigned a3,
    unsigned b0, unsigned b1)
{
    asm("mma.sync.aligned.m16n8k8.row.col.f32.tf32.tf32.f32 "
        "{%0,%1,%2,%3}, {%4,%5,%6,%7}, {%8,%9}, {%0,%1,%2,%3};"
        : "+f"(c[0]), "+f"(c[1]), "+f"(c[2]), "+f"(c[3])
        : "r"(a0), "r"(a1), "r"(a2), "r"(a3), "r"(b0), "r"(b1));
}
#define FU(x) __float_as_uint(x)

// ---------------- kernel 1: embW = emb @ Wx + b  (TF32 tensor GEMM) ---------
// BM=128, BN=64, BK=32. 256 threads = 8 warps; warp w -> rows [16w,16w+16),
// all 64 cols (8 n8-tiles). Fragment map identical to the validated rnn one.
// R16 BUG FIX: Bs was declared [32][40] but tile is 32x64 -> OOB smem writes.
#define EMB_BK 32
__global__ __launch_bounds__(256) void embw_gemm(
    const float* __restrict__ A,    // emb [M][512]
    const float* __restrict__ B,    // Wx  [512][512]
    const float* __restrict__ bias, // b [512]
    int M)
{
    __shared__ __align__(16) float As[128][36];     // [m][k] pad 36 (4 mod 32)
    __shared__ __align__(16) float Bs[EMB_BK][72];  // [k][n] 64+8 pad (8 mod 32)

    const int tid  = threadIdx.x;
    const int warp = tid >> 5;
    const int lane = tid & 31;
    const int g = lane >> 2, t = lane & 3;
    const int row0 = blockIdx.y * 128;
    const int col0 = blockIdx.x * 64;
    const int mr = warp << 4;

    float c[8][4];
    #pragma unroll
    for (int i = 0; i < 8; i++)
        #pragma unroll
        for (int j = 0; j < 4; j++) c[i][j] = 0.f;

    for (int k0 = 0; k0 < DIM; k0 += EMB_BK) {
        // stage A tile 128x32 (tf32-rounded): 1024 float4, 4 per thread
        #pragma unroll
        for (int i = 0; i < 4; i++) {
            int idx = tid + (i << 8);
            int r  = idx >> 3;
            int k4 = (idx & 7) << 2;
            float4 v = make_float4(0.f, 0.f, 0.f, 0.f);
            if (row0 + r < M)
                v = *(const float4*)(A + (size_t)(row0 + r) * DIM + k0 + k4);
            *(float4*)&As[r][k4] =
                make_float4(tf32r(v.x), tf32r(v.y), tf32r(v.z), tf32r(v.w));
        }
        // stage B tile 32x64 (tf32-rounded): 512 float4, 2 per thread
        #pragma unroll
        for (int i = 0; i < 2; i++) {
            int idx = tid + (i << 8);
            int kk = idx >> 4;
            int n4 = (idx & 15) << 2;
            float4 v = *(const float4*)(B + (size_t)(k0 + kk) * DIM + col0 + n4);
            *(float4*)&Bs[kk][n4] =
                make_float4(tf32r(v.x), tf32r(v.y), tf32r(v.z), tf32r(v.w));
        }
        __syncthreads();

        #pragma unroll
        for (int kk8 = 0; kk8 < EMB_BK / 8; kk8++) {
            int k = kk8 << 3;
            unsigned a0 = FU(As[mr + g    ][k + t]);
            unsigned a1 = FU(As[mr + g + 8][k + t]);
            unsigned a2 = FU(As[mr + g    ][k + t + 4]);
            unsigned a3 = FU(As[mr + g + 8][k + t + 4]);
            #pragma unroll
            for (int i = 0; i < 8; i++) {
                unsigned b0 = FU(Bs[k + t    ][(i << 3) + g]);
                unsigned b1 = FU(Bs[k + t + 4][(i << 3) + g]);
                mma_tf32(c[i], a0, a1, a2, a3, b0, b1);
            }
        }
        __syncthreads();
    }

    int r0g = row0 + mr + g, r1g = r0g + 8;
    #pragma unroll
    for (int i = 0; i < 8; i++) {
        int cb = col0 + (i << 3) + 2 * t;
        float2 bb = *(const float2*)(bias + cb);
        if (r0g < M)
            *(float2*)(g_embW + (size_t)r0g * DIM + cb) =
                make_float2(c[i][0] + bb.x, c[i][1] + bb.y);
        if (r1g < M)
            *(float2*)(g_embW + (size_t)r1g * DIM + cb) =
                make_float2(c[i][2] + bb.x, c[i][3] + bb.y);
    }
}

// ---------------- kernel 2: persistent RNN recurrence (TF32, packed) --------
// 128 CTAs: blockIdx = rg*8 + cg.  128 threads, 4 warps.
// h and Wh live in smem in MMA-FRAGMENT ORDER: one LDS.128 delivers a full
// A-fragment (hsP) or B-fragment pair (wtP) -> per k8-iter: 2 LDS.128 + 2 MMA.
// g_h also stores the permuted layout, so staging is a linear float4 copy.
// Sync fabric: R11/R14-proven (sector-padded flags, bar.sync + st.release,
// eager per-chunk polling by staging threads).
__global__ __launch_bounds__(RNN_THREADS, 1) void rnn_recur(
    const int*   __restrict__ x,    // [256][512] tokens
    const float* __restrict__ Wh)   // [512][512]
{
    extern __shared__ __align__(16) float smem[];
    float* wtP = smem;                 // [warp][k8][lane][4] = {b00,b01,b10,b11}
    float* hsP = smem + WTP_FLOATS;    // [k8][lane][4] = {a0,a1,a2,a3}

    const int tid  = threadIdx.x;
    const int warp = tid >> 5;
    const int lane = tid & 31;
    const int rg   = blockIdx.x >> 3;
    const int cg   = blockIdx.x & 7;
    const int col0 = cg * 64;
    const int row0 = rg * 16;

    // one-time wtP init: dest-indexed gather from Wh (tf32-rounded)
    for (int idx = tid; idx < WTP_FLOATS; idx += RNN_THREADS) {
        int q  = idx & 3;
        int ln = (idx >> 2) & 31;
        int k8 = (idx >> 7) & 63;
        int w  = idx >> 13;
        int gg = ln >> 2, tt = ln & 3;
        int cc = (w << 4) + ((q >> 1) << 3) + gg;      // local col in [0,64)
        int dd = (k8 << 3) + tt + ((q & 1) << 2);      // k index
        wtP[idx] = tf32r(Wh[(size_t)dd * DIM + col0 + cc]);
    }

    // mma thread mapping (R15-validated)
    const int g = lane >> 2, t = lane & 3;
    const int nb0 = warp << 4;
    const int d0  = col0 + nb0 + 2 * t;   // global col of c0 pair
    const int d1  = d0 + 8;               // global col of c1 pair
    const int gr0 = row0 + g, gr1 = gr0 + 8;

    // permuted write base for own h outputs:
    // h00:+0  h01:+4  h02:+1  h03:+5  h10:+128  h11:+132  h12:+129  h13:+133
    const int pa0 = ((d0 >> 3) << 7) + (((g << 2) + (d0 & 3)) << 2)
                  + (((d0 >> 2) & 1) << 1);

    // staging: 16 threads per source chunk; own chunk (scc==cg) produced locally
    const int scc = tid >> 4;              // source chunk 0..7
    const int sj  = tid & 15;
    const bool stager = (scc != cg);
    const unsigned* mychunkflag = &g_flags[rg][scc << 3];

    unsigned* myflag = &g_flags[rg][cg << 3];
    const unsigned base = ldflag_acq(myflag);   // replay-safe monotonic base

    __syncthreads();

    for (int l = 0; l < SEQL; l++) {
        // prefetch tokens + xin early (independent of sync / h)
        int tok0 = __ldg(x + (size_t)gr0 * SEQL + l);
        int tok1 = __ldg(x + (size_t)gr1 * SEQL + l);
        const float* e0 = g_embW + (size_t)tok0 * DIM;
        const float* e1 = g_embW + (size_t)tok1 * DIM;
        float2 x00 = __ldg((const float2*)(e0 + d0));
        float2 x01 = __ldg((const float2*)(e0 + d1));
        float2 x10 = __ldg((const float2*)(e1 + d0));
        float2 x11 = __ldg((const float2*)(e1 + d1));

        // accumulators seeded with xin
        float c0[4] = {x00.x, x00.y, x10.x, x10.y};
        float c1[4] = {x01.x, x01.y, x11.x, x11.y};

        if (l > 0) {
            // ---- eager staging: poll source chunk's flag, linear 4KB copy ----
            if (stager) {
                unsigned target = base + (unsigned)l;
                while ((int)(ldflag_acq(mychunkflag) - target) < 0) { }
                const float4* src = (const float4*)(g_h
                    + ((((size_t)(l & 1) << 4) + rg) << 13)) + (scc << 8) + sj;
                float4* dst = (float4*)hsP + (scc << 8) + sj;
                #pragma unroll
                for (int k = 0; k < 16; k++)
                    dst[k << 4] = __ldcg(src + (k << 4));
            }
            __syncthreads();

            // ---- h @ Wh: 64 k8-iters, 2 LDS.128 + 2 MMA each; split chains ----
            float c0b[4] = {0.f, 0.f, 0.f, 0.f};
            float c1b[4] = {0.f, 0.f, 0.f, 0.f};
            const float4* hA = (const float4*)hsP + lane;
            const float4* wB = (const float4*)wtP + (warp << 11) + lane;

            #pragma unroll 8
            for (int k8 = 0; k8 < 64; k8 += 2) {
                float4 av = hA[k8 << 5];
                float4 bv = wB[k8 << 5];
                mma_tf32(c0, FU(av.x), FU(av.y), FU(av.z), FU(av.w),
                         FU(bv.x), FU(bv.y));
                mma_tf32(c1, FU(av.x), FU(av.y), FU(av.z), FU(av.w),
                         FU(bv.z), FU(bv.w));
                float4 av2 = hA[(k8 + 1) << 5];
                float4 bv2 = wB[(k8 + 1) << 5];
                mma_tf32(c0b, FU(av2.x), FU(av2.y), FU(av2.z), FU(av2.w),
                         FU(bv2.x), FU(bv2.y));
                mma_tf32(c1b, FU(av2.x), FU(av2.y), FU(av2.z), FU(av2.w),
                         FU(bv2.z), FU(bv2.w));
            }
            #pragma unroll
            for (int i = 0; i < 4; i++) { c0[i] += c0b[i]; c1[i] += c1b[i]; }
        }

        // tanh + tf32 rounding (stored h exactly representable in tf32)
        float h00 = tf32r(tanhfast(c0[0]));
        float h01 = tf32r(tanhfast(c0[1]));
        float h02 = tf32r(tanhfast(c0[2]));
        float h03 = tf32r(tanhfast(c0[3]));
        float h10 = tf32r(tanhfast(c1[0]));
        float h11 = tf32r(tanhfast(c1[1]));
        float h12 = tf32r(tanhfast(c1[2]));
        float h13 = tf32r(tanhfast(c1[3]));

        // permuted global stores (consumed linearly by sibling stagers)
        float* gdst = g_h + ((((size_t)((l + 1) & 1) << 4) + rg) << 13);
        __stcg(gdst + pa0,       h00);
        __stcg(gdst + pa0 + 4,   h01);
        __stcg(gdst + pa0 + 1,   h02);
        __stcg(gdst + pa0 + 5,   h03);
        __stcg(gdst + pa0 + 128, h10);
        __stcg(gdst + pa0 + 132, h11);
        __stcg(gdst + pa0 + 129, h12);
        __stcg(gdst + pa0 + 133, h13);

        // ---- publish: CTA barrier (cta-scope fence) then release store ----
        __syncthreads();
        if (tid == 0) stflag_rel(myflag, base + (unsigned)(l + 1));

        // own chunk into hsP (ordered by next staging __syncthreads; stagers
        // never touch this CTA's own 4KB region)
        hsP[pa0]       = h00;
        hsP[pa0 + 4]   = h01;
        hsP[pa0 + 1]   = h02;
        hsP[pa0 + 5]   = h03;
        hsP[pa0 + 128] = h10;
        hsP[pa0 + 132] = h11;
        hsP[pa0 + 129] = h12;
        hsP[pa0 + 133] = h13;
    }
    // flags end at base+512: next launch re-reads as its new base (no reset)
}

// ---------------- kernel 3: logits + softmax (reads permuted h) -------------
__global__ __launch_bounds__(256) void softmax_kernel(
    const float* __restrict__ Wd,   // [512][20]
    const float* __restrict__ bd,   // [20]
    float* __restrict__ out)        // [256][20]
{
    int b    = blockIdx.x * 8 + (threadIdx.x >> 5);
    int lane = threadIdx.x & 31;
    if (b >= BATCH) return;

    const int rg = b >> 4;
    const int r  = b & 15;
    const float* h = g_h + ((size_t)rg << 13);   // final h is in buffer 0

    float acc[NCLS];
    #pragma unroll
    for (int c = 0; c < NCLS; c++) acc[c] = 0.f;

    for (int d = lane; d < DIM; d += 32) {
        float hv = __ldcg(h + perm_addr(r, d));
        #pragma unroll
        for (int c = 0; c < NCLS; c++)
            acc[c] += hv * Wd[d * NCLS + c];
    }
    #pragma unroll
    for (int c = 0; c < NCLS; c++) {
        #pragma unroll
        for (int off = 16; off > 0; off >>= 1)
            acc[c] += __shfl_xor_sync(0xFFFFFFFFu, acc[c], off);
    }
    if (lane == 0) {
        float logit[NCLS];
        float m = -1e30f;
        #pragma unroll
        for (int c = 0; c < NCLS; c++) {
            logit[c] = acc[c] + bd[c];
            m = fmaxf(m, logit[c]);
        }
        float s = 0.f;
        #pragma unroll
        for (int c = 0; c < NCLS; c++) {
            logit[c] = expf(logit[c] - m);
            s += logit[c];
        }
        float inv = 1.0f / s;
        #pragma unroll
        for (int c = 0; c < NCLS; c++)
            out[b * NCLS + c] = logit[c] * inv;
    }
}

// ---------------- launch ----------------------------------------------------
extern "C" void kernel_launch(void* const* d_in, const int* in_sizes, int n_in,
                              void* d_out, int out_size)
{
    const int*   x   = (const int*)  d_in[0];
    const float* emb = (const float*)d_in[1];
    const float* Wx  = (const float*)d_in[2];
    const float* Wh  = (const float*)d_in[3];
    const float* b   = (const float*)d_in[4];
    const float* Wd  = (const float*)d_in[5];
    const float* bd  = (const float*)d_in[6];
    float* out = (float*)d_out;

    // 1) embW = emb @ Wx + b  (TF32 tensor GEMM)
    embw_gemm<<<dim3(DIM / 64, (VOCAB + 127) / 128), 256>>>(emb, Wx, b, VOCAB);

    // 2) persistent recurrence (128 CTAs x 128 threads, 160KB smem, all resident)
    cudaFuncSetAttribute(rnn_recur, cudaFuncAttributeMaxDynamicSharedMemorySize,
                         RNN_SMEM_BYTES);
    rnn_recur<<<128, RNN_THREADS, RNN_SMEM_BYTES>>>(x, Wh);

    // 3) logits + softmax
    softmax_kernel<<<(BATCH + 7) / 8, 256>>>(Wd, bd, out);
}